// round 1
// baseline (speedup 1.0000x reference)
#include <cuda_runtime.h>
#include <math.h>

#define H 2048
#define S 32
#define NHEAD 8
#define DHD 256

// ---------------- scratch (no allocation allowed -> device globals) ----------
__device__ float g_x[S * H];
__device__ float g_y[S * H];
__device__ float g_qkv[S * 3 * H];
__device__ float g_attn[S * H];
__device__ float g_ff[S * 4 * H];
__device__ float g_part[8 * 32 * 8192];   // max split-K partial buffer (8.4 MB)
__device__ float g_v1[H];
__device__ float g_v2[H];
__device__ float g_h[1024];

__device__ __forceinline__ float gelu_f(float v) {
    return 0.5f * v * (1.0f + erff(v * 0.70710678118654752f));
}

// ---------------- GEMM: C[32,N] partial = A[32,K-slice] @ B[N,K-slice]^T -----
// B is row-major [N][K] (torch/jax Linear weight layout). Split-K over grid.y.
#define BM 32
#define BN 256
#define BK 16

__global__ __launch_bounds__(128) void gemm32(
    const float* __restrict__ A, const float* __restrict__ B,
    float* __restrict__ Cp, int K, int kchunk)
{
    const int N  = gridDim.x * BN;
    const int n0 = blockIdx.x * BN;
    const int k0 = blockIdx.y * kchunk;

    __shared__ float As[BK][BM];
    __shared__ float Bs[BK][BN];

    const int tid = threadIdx.x;
    const int tx  = tid & 31;   // n-group (lane)
    const int ty  = tid >> 5;   // m-group (warp)

    float acc[8][8];
#pragma unroll
    for (int i = 0; i < 8; i++)
#pragma unroll
        for (int j = 0; j < 8; j++) acc[i][j] = 0.f;

    const int am = tid >> 2;
    const int ak = (tid & 3) * 4;

    for (int kt = 0; kt < kchunk; kt += BK) {
        // A tile 32x16 (transposed into As[k][m])
        {
            float4 a = *(const float4*)&A[(size_t)am * K + k0 + kt + ak];
            As[ak + 0][am] = a.x; As[ak + 1][am] = a.y;
            As[ak + 2][am] = a.z; As[ak + 3][am] = a.w;
        }
        // B tile 256x16 (transposed into Bs[k][n]); 2 rows per thread
#pragma unroll
        for (int r = 0; r < 2; r++) {
            int n = tid * 2 + r;
            const float* brow = B + (size_t)(n0 + n) * K + k0 + kt;
#pragma unroll
            for (int q = 0; q < 4; q++) {
                float4 b = *(const float4*)(brow + q * 4);
                Bs[q * 4 + 0][n] = b.x; Bs[q * 4 + 1][n] = b.y;
                Bs[q * 4 + 2][n] = b.z; Bs[q * 4 + 3][n] = b.w;
            }
        }
        __syncthreads();
#pragma unroll
        for (int k = 0; k < BK; k++) {
            float av[8], bv[8];
            *(float4*)&av[0] = *(const float4*)&As[k][ty * 4];        // broadcast
            *(float4*)&av[4] = *(const float4*)&As[k][16 + ty * 4];   // broadcast
            *(float4*)&bv[0] = *(const float4*)&Bs[k][tx * 4];        // conflict-free
            *(float4*)&bv[4] = *(const float4*)&Bs[k][128 + tx * 4];  // conflict-free
#pragma unroll
            for (int i = 0; i < 8; i++)
#pragma unroll
                for (int j = 0; j < 8; j++)
                    acc[i][j] = fmaf(av[i], bv[j], acc[i][j]);
        }
        __syncthreads();
    }

    float* cp = Cp + (size_t)blockIdx.y * 32 * N;
#pragma unroll
    for (int i = 0; i < 8; i++) {
        int m = (i < 4) ? (ty * 4 + i) : (16 + ty * 4 + i - 4);
        *(float4*)&cp[(size_t)m * N + n0 + tx * 4]       = *(float4*)&acc[i][0];
        *(float4*)&cp[(size_t)m * N + n0 + 128 + tx * 4] = *(float4*)&acc[i][4];
    }
}

// ---------------- split-K combine + bias (+ residual) (+ gelu) ---------------
__global__ void combine_kernel(
    const float* __restrict__ Cp, int KS, int N,
    const float* __restrict__ bias, const float* __restrict__ resid,
    float* __restrict__ out, int act)
{
    int idx = blockIdx.x * 256 + threadIdx.x;
    int total = 32 * N;
    if (idx >= total) return;
    float s = 0.f;
    for (int k = 0; k < KS; k++) s += Cp[(size_t)k * total + idx];
    s += bias[idx & (N - 1)];
    if (resid) s += resid[idx];
    if (act) s = gelu_f(s);
    out[idx] = s;
}

// ---------------- GEMV: out[N] = W[N,K] @ x[K] + b (warp per row) ------------
__global__ void gemv_kernel(
    const float* __restrict__ x, const float* __restrict__ W,
    const float* __restrict__ bias, float* __restrict__ out, int K, int act)
{
    int n = blockIdx.x * 8 + (threadIdx.x >> 5);
    int lane = threadIdx.x & 31;
    const float* w = W + (size_t)n * K;
    float s = 0.f;
    for (int k = lane * 4; k < K; k += 128) {
        float4 a = *(const float4*)&x[k];
        float4 b = *(const float4*)&w[k];
        s += a.x * b.x + a.y * b.y + a.z * b.z + a.w * b.w;
    }
#pragma unroll
    for (int o = 16; o; o >>= 1) s += __shfl_xor_sync(0xffffffffu, s, o);
    if (lane == 0) {
        s += bias[n];
        if (act) s = gelu_f(s);
        out[n] = s;
    }
}

// ---------------- LayerNorm over H=2048 per row (optional broadcast add) -----
__global__ void ln_kernel(
    const float* __restrict__ in, const float* __restrict__ addv,
    const float* __restrict__ gg, const float* __restrict__ bb,
    float* __restrict__ out)
{
    __shared__ float row[H];
    __shared__ float red1[8];
    __shared__ float red2[8];
    int r = blockIdx.x, tid = threadIdx.x;
    int lane = tid & 31, w = tid >> 5;

    float lsum = 0.f;
#pragma unroll
    for (int sgrp = 0; sgrp < 2; sgrp++) {
        int j = tid * 4 + sgrp * 1024;
        float4 v = *(const float4*)&in[(size_t)r * H + j];
        if (addv) {
            float4 a = *(const float4*)&addv[j];
            v.x += a.x; v.y += a.y; v.z += a.z; v.w += a.w;
        }
        *(float4*)&row[j] = v;
        lsum += v.x + v.y + v.z + v.w;
    }
#pragma unroll
    for (int o = 16; o; o >>= 1) lsum += __shfl_xor_sync(0xffffffffu, lsum, o);
    if (lane == 0) red1[w] = lsum;
    __syncthreads();
    float mean = (red1[0] + red1[1] + red1[2] + red1[3] +
                  red1[4] + red1[5] + red1[6] + red1[7]) * (1.0f / H);

    float lsq = 0.f;
#pragma unroll
    for (int sgrp = 0; sgrp < 2; sgrp++) {
        int j = tid * 4 + sgrp * 1024;
        float4 v = *(const float4*)&row[j];
        float dx = v.x - mean, dy = v.y - mean, dz = v.z - mean, dw = v.w - mean;
        lsq += dx * dx + dy * dy + dz * dz + dw * dw;
    }
#pragma unroll
    for (int o = 16; o; o >>= 1) lsq += __shfl_xor_sync(0xffffffffu, lsq, o);
    if (lane == 0) red2[w] = lsq;
    __syncthreads();
    float var = (red2[0] + red2[1] + red2[2] + red2[3] +
                 red2[4] + red2[5] + red2[6] + red2[7]) * (1.0f / H);
    float inv = rsqrtf(var + 1e-5f);

#pragma unroll
    for (int sgrp = 0; sgrp < 2; sgrp++) {
        int j = tid * 4 + sgrp * 1024;
        float4 v = *(const float4*)&row[j];
        float4 gv = *(const float4*)&gg[j];
        float4 bv = *(const float4*)&bb[j];
        float4 o;
        o.x = (v.x - mean) * inv * gv.x + bv.x;
        o.y = (v.y - mean) * inv * gv.y + bv.y;
        o.z = (v.z - mean) * inv * gv.z + bv.z;
        o.w = (v.w - mean) * inv * gv.w + bv.w;
        *(float4*)&out[(size_t)r * H + j] = o;
    }
}

// ---------------- self-attention (per head, per 8-row query group) -----------
__global__ void attn_kernel(const float* __restrict__ qkv, float* __restrict__ o)
{
    int h = blockIdx.x, bq = blockIdx.y;  // 8 heads x 4 query groups of 8 rows
    int tid = threadIdx.x;
    __shared__ float sc[8][32];

    int il = tid >> 5;               // local row 0..7 (warp)
    int i = bq * 8 + il;
    int j = tid & 31;                // key index = lane
    const float* q = qkv + (size_t)i * (3 * H) + h * DHD;
    const float* k = qkv + (size_t)j * (3 * H) + H + h * DHD;
    float s = 0.f;
#pragma unroll 8
    for (int d = 0; d < DHD; d += 4) {
        float4 a = *(const float4*)&q[d];
        float4 b = *(const float4*)&k[d];
        s += a.x * b.x + a.y * b.y + a.z * b.z + a.w * b.w;
    }
    s *= 0.0625f;  // 1/sqrt(256)
    float mx = s;
#pragma unroll
    for (int off = 16; off; off >>= 1) mx = fmaxf(mx, __shfl_xor_sync(0xffffffffu, mx, off));
    float p = expf(s - mx);
    float sum = p;
#pragma unroll
    for (int off = 16; off; off >>= 1) sum += __shfl_xor_sync(0xffffffffu, sum, off);
    sc[il][j] = p / sum;
    __syncthreads();

    // o[i][d] = sum_j p[i][j] * v[j][d] : 8 rows x 256 d = 2048 outs / 256 thr
#pragma unroll
    for (int r = 0; r < 8; r++) {
        int u = tid + 256 * r;
        int ir = u >> 8;       // 0..7
        int d = u & 255;
        const float* vb = qkv + 2 * H + h * DHD + d;
        float acc = 0.f;
#pragma unroll
        for (int jj = 0; jj < 32; jj++)
            acc = fmaf(sc[ir][jj], vb[(size_t)jj * (3 * H)], acc);
        o[(size_t)(bq * 8 + ir) * H + h * DHD + d] = acc;
    }
}

// ---------------- decoder input embedding ------------------------------------
__global__ void embed_kernel(const int* __restrict__ tb,
                             const float* __restrict__ bemb,
                             const float* __restrict__ pemb,
                             float* __restrict__ x)
{
    int idx = blockIdx.x * 256 + threadIdx.x;   // 32*2048
    int m = idx >> 11, j = idx & 2047;
    int tok = (m == 0) ? 256 : tb[m - 1];       // START = V = 256
    x[idx] = bemb[(size_t)tok * H + j] + pemb[idx];
}

// ---------------- size predictor head 2 + softmax -----------------------------
__global__ void sp2_softmax(const float* __restrict__ hv, const float* __restrict__ W,
                            const float* __restrict__ bias, float* __restrict__ out)
{
    __shared__ float lg[33];
    int tid = threadIdx.x, w = tid >> 5, lane = tid & 31;
    for (int n = w; n < 33; n += 8) {
        const float* wr = W + (size_t)n * 1024;
        float s = 0.f;
        for (int k = lane * 4; k < 1024; k += 128) {
            float4 a = *(const float4*)&hv[k];
            float4 b = *(const float4*)&wr[k];
            s += a.x * b.x + a.y * b.y + a.z * b.z + a.w * b.w;
        }
#pragma unroll
        for (int o = 16; o; o >>= 1) s += __shfl_xor_sync(0xffffffffu, s, o);
        if (lane == 0) lg[n] = s + bias[n];
    }
    __syncthreads();
    if (tid == 0) {
        float mx = -1e30f;
        for (int n = 0; n < 33; n++) mx = fmaxf(mx, lg[n]);
        float sum = 0.f;
        for (int n = 0; n < 33; n++) { float e = expf(lg[n] - mx); lg[n] = e; sum += e; }
        float inv = 1.0f / sum;
        for (int n = 0; n < 33; n++) out[n] = lg[n] * inv;
    }
}

// =============================================================================
extern "C" void kernel_launch(void* const* d_in, const int* in_sizes, int n_in,
                              void* d_out, int out_size)
{
    const float* pe     = (const float*)d_in[0];
    const int*   tb     = (const int*)  d_in[1];
    const float* sp_w1  = (const float*)d_in[2];
    const float* sp_b1  = (const float*)d_in[3];
    const float* sp_w2  = (const float*)d_in[4];
    const float* sp_b2  = (const float*)d_in[5];
    const float* bemb   = (const float*)d_in[6];
    const float* pemb   = (const float*)d_in[7];
    const float* proj_w = (const float*)d_in[8];
    const float* proj_b = (const float*)d_in[9];
    const float* sa_in_w  = (const float*)d_in[10];
    const float* sa_in_b  = (const float*)d_in[11];
    const float* sa_out_w = (const float*)d_in[12];
    const float* sa_out_b = (const float*)d_in[13];
    const float* ca_in_w  = (const float*)d_in[14];
    const float* ca_in_b  = (const float*)d_in[15];
    const float* ca_out_w = (const float*)d_in[16];
    const float* ca_out_b = (const float*)d_in[17];
    const float* ff_w1 = (const float*)d_in[18];
    const float* ff_b1 = (const float*)d_in[19];
    const float* ff_w2 = (const float*)d_in[20];
    const float* ff_b2 = (const float*)d_in[21];
    const float* ln1_g = (const float*)d_in[22];
    const float* ln1_b = (const float*)d_in[23];
    const float* ln2_g = (const float*)d_in[24];
    const float* ln2_b = (const float*)d_in[25];
    const float* ln3_g = (const float*)d_in[26];
    const float* ln3_b = (const float*)d_in[27];

    float *x, *y, *qkv, *attn, *ff, *part, *v1, *v2, *hbuf;
    cudaGetSymbolAddress((void**)&x, g_x);
    cudaGetSymbolAddress((void**)&y, g_y);
    cudaGetSymbolAddress((void**)&qkv, g_qkv);
    cudaGetSymbolAddress((void**)&attn, g_attn);
    cudaGetSymbolAddress((void**)&ff, g_ff);
    cudaGetSymbolAddress((void**)&part, g_part);
    cudaGetSymbolAddress((void**)&v1, g_v1);
    cudaGetSymbolAddress((void**)&v2, g_v2);
    cudaGetSymbolAddress((void**)&hbuf, g_h);

    float* out = (float*)d_out;

    // size predictor: h = gelu(pe @ sp_w1^T + b), softmax(h @ sp_w2^T + b)
    gemv_kernel<<<1024 / 8, 256>>>(pe, sp_w1, sp_b1, hbuf, 2048, 1);
    sp2_softmax<<<1, 256>>>(hbuf, sp_w2, sp_b2, out);

    // decoder input
    embed_kernel<<<(S * H) / 256, 256>>>(tb, bemb, pemb, x);

    for (int l = 0; l < 3; l++) {
        // --- self attention ---
        gemm32<<<dim3(24, 8), 128>>>(x, sa_in_w + (size_t)l * 3 * H * H, part, H, 256);
        combine_kernel<<<(32 * 6144) / 256, 256>>>(part, 8, 6144, sa_in_b + (size_t)l * 3 * H,
                                                   nullptr, qkv, 0);
        attn_kernel<<<dim3(8, 4), 256>>>(qkv, attn);
        gemm32<<<dim3(8, 16), 128>>>(attn, sa_out_w + (size_t)l * H * H, part, H, 128);
        combine_kernel<<<(32 * H) / 256, 256>>>(part, 16, H, sa_out_b + (size_t)l * H, x, y, 0);
        ln_kernel<<<32, 256>>>(y, nullptr, ln1_g + (size_t)l * H, ln1_b + (size_t)l * H, x);

        // --- cross attention (collapses: seq-len-1 memory => broadcast vector) ---
        gemv_kernel<<<H / 8, 256>>>(pe, ca_in_w + ((size_t)l * 3 * H + 2 * H) * H,
                                    ca_in_b + (size_t)l * 3 * H + 2 * H, v1, H, 0);
        gemv_kernel<<<H / 8, 256>>>(v1, ca_out_w + (size_t)l * H * H,
                                    ca_out_b + (size_t)l * H, v2, H, 0);
        ln_kernel<<<32, 256>>>(x, v2, ln2_g + (size_t)l * H, ln2_b + (size_t)l * H, x);

        // --- feed forward ---
        gemm32<<<dim3(32, 8), 128>>>(x, ff_w1 + (size_t)l * 4 * H * H, part, H, 256);
        combine_kernel<<<(32 * 8192) / 256, 256>>>(part, 8, 8192, ff_b1 + (size_t)l * 4 * H,
                                                   nullptr, ff, 1);
        gemm32<<<dim3(8, 16), 128>>>(ff, ff_w2 + (size_t)l * H * 4 * H, part, 4 * H, 512);
        combine_kernel<<<(32 * H) / 256, 256>>>(part, 16, H, ff_b2 + (size_t)l * H, x, y, 0);
        ln_kernel<<<32, 256>>>(y, nullptr, ln3_g + (size_t)l * H, ln3_b + (size_t)l * H, x);
    }

    // byte logits
    gemm32<<<dim3(1, 32), 128>>>(x, proj_w, part, H, 64);
    combine_kernel<<<(32 * 256) / 256, 256>>>(part, 32, 256, proj_b, nullptr, out + 33, 0);
}